// round 2
// baseline (speedup 1.0000x reference)
#include <cuda_runtime.h>
#include <math.h>

#define BB 16
#define AA 3
#define SDIM 80
#define NC 80
#define NT 32
#define SSP (SDIM * SDIM)             // 6400
#define CH (5 + NC)                   // 85
#define CELLS (BB * AA * SSP)         // 307200
#define NTHR 512
#define NBLK (CELLS / 4 / NTHR)       // 150 (float4 per thread)
#define EPSF 1e-7f
#define IMG 640.0f
#define STRIDEF 8.0f

// self-resetting scratch (zero at module load; last block restores zero)
__device__ double        g_conf_sum = 0.0;
__device__ unsigned int  g_count = 0;

__device__ __forceinline__ float softplusf(float x) {
    // stable: max(x,0) + log1p(exp(-|x|)); fast exp is fine at 1e-3 tolerance
    return fmaxf(x, 0.0f) + log1pf(__expf(-fabsf(x)));
}
__device__ __forceinline__ float sigmoidf(float x) {
    return 1.0f / (1.0f + __expf(-x));
}

// block-wide float sum, result valid in thread 0. Caller must not reuse `red`
// until after the trailing __syncthreads inside.
__device__ __forceinline__ float block_sum(float v, float* red, int tid) {
    #pragma unroll
    for (int o = 16; o > 0; o >>= 1) v += __shfl_down_sync(0xffffffffu, v, o);
    if ((tid & 31) == 0) red[tid >> 5] = v;
    __syncthreads();
    if (tid < 32) {
        v = (tid < (NTHR >> 5)) ? red[tid] : 0.0f;
        #pragma unroll
        for (int o = 8; o > 0; o >>= 1) v += __shfl_down_sync(0xffffffffu, v, o);
    }
    __syncthreads();
    return v;
}

__device__ __forceinline__ void assign_target(
    const float* __restrict__ tbox, const float* aw, const float* ah,
    int b, int m, int& a, int& gi, int& gj)
{
    const float* p = tbox + (size_t)(b * NT + m) * 4;
    float x = p[0], y = p[1], w = p[2], h = p[3];
    gi = min(max((int)floorf(x * (float)SDIM), 0), SDIM - 1);
    gj = min(max((int)floorf(y * (float)SDIM), 0), SDIM - 1);
    float tw = w * IMG, th = h * IMG;
    float best = -1.0f; a = 0;
    #pragma unroll
    for (int k = 0; k < AA; k++) {
        float inter = fminf(tw, aw[k]) * fminf(th, ah[k]);
        float un = tw * th + aw[k] * ah[k] - inter;
        float r = inter / un;
        if (r > best) { best = r; a = k; }   // first-max wins (jnp.argmax)
    }
}

__device__ __forceinline__ float ciou_f(
    float px1, float py1, float px2, float py2,
    float tx1, float ty1, float tx2, float ty2)
{
    float iw = fmaxf(fminf(px2, tx2) - fmaxf(px1, tx1), 0.0f);
    float ih = fmaxf(fminf(py2, ty2) - fmaxf(py1, ty1), 0.0f);
    float inter = iw * ih;
    float pa = fmaxf(px2 - px1, 0.0f) * fmaxf(py2 - py1, 0.0f);
    float ta = fmaxf(tx2 - tx1, 0.0f) * fmaxf(ty2 - ty1, 0.0f);
    float un = pa + ta - inter + EPSF;
    float iou = inter / un;
    float dx = 0.5f * (px1 + px2) - 0.5f * (tx1 + tx2);
    float dy = 0.5f * (py1 + py2) - 0.5f * (ty1 + ty2);
    float cd = dx * dx + dy * dy;
    float ew = fmaxf(px2, tx2) - fminf(px1, tx1);
    float eh = fmaxf(py2, ty2) - fminf(py1, ty1);
    float ed = ew * ew + eh * eh + EPSF;
    float pw = fmaxf(px2 - px1, EPSF);
    float ph = fmaxf(py2 - py1, EPSF);
    float tw = fmaxf(tx2 - tx1, EPSF);
    float th = fmaxf(ty2 - ty1, EPSF);
    float da = atanf(tw / th) - atanf(pw / ph);
    float v = (4.0f / ((float)M_PI * (float)M_PI)) * da * da;
    float alpha = v / (1.0f - iou + v + EPSF);
    return iou - cd / ed - alpha * v;
}

__global__ void __launch_bounds__(NTHR)
yolo_fused(const float* __restrict__ preds,
           const float* __restrict__ anchors,
           const int* __restrict__ tcls,
           const float* __restrict__ tbox,
           float* __restrict__ out)
{
    __shared__ float red[16];
    __shared__ int   s_cell[NTHR];
    __shared__ int   s_islast;

    int tid = threadIdx.x;

    // ── Phase 1: Σ softplus(conf) over all 307200 cells (float4 coalesced) ──
    int idx = blockIdx.x * NTHR + tid;         // 0..76799
    int plane = idx / (SSP / 4);               // b*3 + a, 48 planes of 1600 f4
    int off4  = idx - plane * (SSP / 4);
    int b = plane / AA, a = plane - AA * b;
    const float4* p4 = (const float4*)(preds +
        ((size_t)(b * (AA * CH) + a * CH + 4)) * SSP);
    float4 v = p4[off4];
    float s = softplusf(v.x) + softplusf(v.y) + softplusf(v.z) + softplusf(v.w);

    float bsum = block_sum(s, red, tid);

    if (tid == 0) {
        atomicAdd(&g_conf_sum, (double)bsum);
        __threadfence();
        unsigned old = atomicAdd(&g_count, 1u);
        s_islast = (old == (unsigned)(NBLK - 1));
    }
    __syncthreads();
    if (!s_islast) return;

    // ── Phase 2 (last block only): sparse obj-cell losses ──
    __threadfence();   // acquire: make all blocks' g_conf_sum adds visible

    float aw[AA], ah[AA];
    #pragma unroll
    for (int k = 0; k < AA; k++) { aw[k] = anchors[2 * k]; ah[k] = anchors[2 * k + 1]; }

    int tb = tid / NT, tn = tid - tb * NT;     // 512 = B*N exactly
    int ta, gi, gj;
    assign_target(tbox, aw, ah, tb, tn, ta, gi, gj);
    int cell = ((tb * AA + ta) * SDIM + gj) * SDIM + gi;
    s_cell[tid] = cell;
    __syncthreads();

    // owner = lowest tid with this cell (within-batch collisions only possible,
    // but scanning whole block is cheap and also catches cross-batch — which
    // cannot collide since b is encoded in cell)
    bool owner = true;
    for (int m = tb * NT; m < tid; m++)
        if (s_cell[m] == cell) { owner = false; break; }

    float f_ciou = 0.f, f_bce_obj = 0.f, f_sp = 0.f, f_cls = 0.f, f_cnt = 0.f;

    if (owner) {
        // rescan this batch's targets: class SET union, box last-write-wins
        unsigned clsbits[3] = {0u, 0u, 0u};
        float wx1 = 0.f, wy1 = 0.f, wx2 = 0.f, wy2 = 0.f;
        for (int m = 0; m < NT; m++) {
            if (s_cell[tb * NT + m] == cell) {
                int c = tcls[tb * NT + m];
                clsbits[c >> 5] |= (1u << (c & 31));
                const float* p = tbox + (size_t)(tb * NT + m) * 4;
                float cx = p[0] * IMG, cy = p[1] * IMG;
                float tw = p[2] * IMG, th = p[3] * IMG;
                wx1 = cx - 0.5f * tw; wy1 = cy - 0.5f * th;
                wx2 = cx + 0.5f * tw; wy2 = cy + 0.5f * th;
            }
        }

        size_t base = ((size_t)tb * (AA * CH) + (size_t)ta * CH) * SSP
                      + (size_t)gj * SDIM + gi;
        float p0 = preds[base];
        float p1 = preds[base + (size_t)SSP];
        float p2 = preds[base + (size_t)2 * SSP];
        float p3 = preds[base + (size_t)3 * SSP];
        float pc = preds[base + (size_t)4 * SSP];

        float pcx = (sigmoidf(p0) + (float)gi) * STRIDEF;
        float pcy = (sigmoidf(p1) + (float)gj) * STRIDEF;
        float pw = aw[ta] * __expf(p2);
        float ph = ah[ta] * __expf(p3);

        f_ciou = ciou_f(pcx - 0.5f * pw, pcy - 0.5f * ph,
                        pcx + 0.5f * pw, pcy + 0.5f * ph,
                        wx1, wy1, wx2, wy2);
        f_sp = softplusf(pc);
        f_bce_obj = f_sp - pc;
        f_cnt = 1.0f;

        float cs = 0.0f;
        #pragma unroll 4
        for (int c = 0; c < NC; c++) {
            float l = preds[base + (size_t)(5 + c) * SSP];
            float tgt = (float)((clsbits[c >> 5] >> (c & 31)) & 1u);
            cs += softplusf(l) - l * tgt;
        }
        f_cls = cs;
    }

    float r_ciou = block_sum(f_ciou, red, tid);
    float r_bce  = block_sum(f_bce_obj, red, tid);
    float r_sp   = block_sum(f_sp, red, tid);
    float r_cls  = block_sum(f_cls, red, tid);
    float r_cnt  = block_sum(f_cnt, red, tid);

    if (tid == 0) {
        double nobj = (double)r_cnt;
        double dn_obj   = fmax(nobj, 1.0);
        double dn_noobj = fmax((double)CELLS - nobj, 1.0);
        double dn_cls   = fmax(nobj * (double)NC, 1.0);

        double loss_ciou      = 1.0 - (double)r_ciou / dn_obj;
        double loss_conf_obj  = (double)r_bce / dn_obj;
        double loss_conf_noobj = (g_conf_sum - (double)r_sp) / dn_noobj;
        double loss_cls       = (double)r_cls / dn_cls;

        out[0] = (float)(loss_ciou + loss_conf_obj
                         + 0.5 * loss_conf_noobj + loss_cls);

        // self-reset scratch for the next (graph-replayed) call
        g_conf_sum = 0.0;
        __threadfence();
        g_count = 0u;
    }
}

extern "C" void kernel_launch(void* const* d_in, const int* in_sizes, int n_in,
                              void* d_out, int out_size)
{
    const float* preds   = (const float*)d_in[0];
    const float* anchors = (const float*)d_in[1];
    const int*   tcls    = (const int*)d_in[2];
    const float* tbox    = (const float*)d_in[3];

    yolo_fused<<<NBLK, NTHR>>>(preds, anchors, tcls, tbox, (float*)d_out);
}